// round 16
// baseline (speedup 1.0000x reference)
#include <cuda_runtime.h>
#include <cuda_fp16.h>
#include <cstdint>

#define BT 8
#define SEQ 4096
#define NST 256
#define DIN 256
#define DOUT 256
#define M_TOT (BT*SEQ)          // 32768
#define CHUNK 64
#define NCHUNK (SEQ/CHUNK)      // 64

typedef unsigned long long u64;
typedef __half f16;

// ---------------- device scratch ----------------
__device__ float g_Ar[NST], g_Ai[NST];
__device__ float g_ALr[NST], g_ALi[NST];
__device__ float g_wr[NST], g_wi[NST];
__device__ f16   g_x16[(size_t)M_TOT*DIN];
__device__ f16   g_W1[512*DIN];                 // [Bbar_r; Bbar_i] fp16
__device__ f16   g_W2[DOUT*512];                // [Cr | -Ci] fp16
__device__ f16   g_u16[(size_t)M_TOT*512];      // u fp16: [:,0:256]=real [:,256:512]=imag
__device__ f16   g_h16[(size_t)M_TOT*512];      // h fp16
__device__ float g_cr[BT*NCHUNK*NST], g_ci[BT*NCHUNK*NST];
__device__ float g_pr[BT*NCHUNK*NST], g_pi[BT*NCHUNK*NST];

// mma.sync m16n8k16 row.col fp16 -> f32 accumulate
__device__ __forceinline__ void hmma(float* d, const uint32_t* a, const uint32_t* b) {
    asm volatile(
        "mma.sync.aligned.m16n8k16.row.col.f32.f16.f16.f32 "
        "{%0,%1,%2,%3}, {%4,%5,%6,%7}, {%8,%9}, {%0,%1,%2,%3};"
        : "+f"(d[0]), "+f"(d[1]), "+f"(d[2]), "+f"(d[3])
        : "r"(a[0]), "r"(a[1]), "r"(a[2]), "r"(a[3]), "r"(b[0]), "r"(b[1]));
}
__device__ __forceinline__ void ldsm_x4(uint32_t* r, uint32_t addr) {
    asm volatile("ldmatrix.sync.aligned.m8n8.x4.shared.b16 {%0,%1,%2,%3}, [%4];"
        : "=r"(r[0]), "=r"(r[1]), "=r"(r[2]), "=r"(r[3]) : "r"(addr));
}
__device__ __forceinline__ void cpa16(uint32_t saddr, const void* g) {
    asm volatile("cp.async.cg.shared.global [%0], [%1], 16;" :: "r"(saddr), "l"(g));
}
__device__ __forceinline__ uint32_t smem_u32(const void* p) {
    uint32_t a;
    asm("{ .reg .u64 t; cvta.to.shared.u64 t, %1; cvt.u32.u64 %0, t; }" : "=r"(a) : "l"(p));
    return a;
}
// swizzled byte offset inside a R x 64 f16 tile
__device__ __forceinline__ uint32_t swz(int row, int g8) {
    return (uint32_t)(row * 64 + ((g8 ^ (row & 7)) * 8)) * 2;
}

// ---------------- setup: per-n scalars only ----------------
__global__ void k_setup(const float* __restrict__ llr, const float* __restrict__ lim,
                        const float* __restrict__ ldt) {
    int n = threadIdx.x;
    float lr = -expf(llr[n]);
    float li = lim[n];
    float dt = expf(ldt[n]);
    dt = fminf(fmaxf(dt, 0.005f), 0.1f);
    float dr = 1.f - 0.5f * dt * lr;
    float di = -0.5f * dt * li;
    float nr = 1.f + 0.5f * dt * lr;
    float ni = 0.5f * dt * li;
    float inv = 1.f / (dr*dr + di*di);
    float Ar = (nr*dr + ni*di) * inv;
    float Ai = (ni*dr - nr*di) * inv;
    g_Ar[n] = Ar; g_Ai[n] = Ai;
    g_wr[n] = dt * dr * inv;
    g_wi[n] = -dt * di * inv;
    float pr = 1.f, pi = 0.f;
    for (int j = 0; j < CHUNK; j++) {
        float t = pr*Ar - pi*Ai;
        pi = pr*Ai + pi*Ar;
        pr = t;
    }
    g_ALr[n] = pr; g_ALi[n] = pi;
}

__global__ __launch_bounds__(256) void k_w1(const float* __restrict__ Bm) {
    int idx = blockIdx.x * blockDim.x + threadIdx.x;   // over 256*256
    int n = idx >> 8, k = idx & 255;
    float b = Bm[idx];
    g_W1[idx]             = __float2half_rn(g_wr[n] * b);
    g_W1[(256+n)*DIN + k] = __float2half_rn(g_wi[n] * b);
}

__global__ void k_w2(const float* __restrict__ Cr, const float* __restrict__ Ci) {
    int idx = blockIdx.x * blockDim.x + threadIdx.x;   // over 256*512
    int d = idx >> 9, k = idx & 511;
    float v = (k < 256) ? Cr[d*256 + k] : -Ci[d*256 + (k - 256)];
    g_W2[idx] = __float2half_rn(v);
}

__global__ __launch_bounds__(256) void k_cvt(const float* __restrict__ x) {
    size_t i = (size_t)(blockIdx.x * blockDim.x + threadIdx.x) * 4;
    float4 v = *(const float4*)&x[i];
    __half2 a = {__float2half_rn(v.x), __float2half_rn(v.y)};
    __half2 b = {__float2half_rn(v.z), __float2half_rn(v.w)};
    *(uint2*)&g_x16[i] = make_uint2(*(uint32_t*)&a, *(uint32_t*)&b);
}

// ---------------- GEMM variant A: 128x128 tile, 4 warps (64x64), 3 CTAs/SM, fp16 out ----------------
#define MT1 128
#define A1_EL (MT1*64)
#define W1_EL (128*64)
#define STG1_EL (A1_EL + W1_EL)
#define G1_SMEM (2*STG1_EL*2)        // 64 KB

__global__ __launch_bounds__(128, 3) void k_gemm1(
    const f16* __restrict__ A, int lda,
    const f16* __restrict__ W,
    f16* __restrict__ out, int ldc, int Kdim)
{
    extern __shared__ f16 smem[];
    const uint32_t sb = smem_u32(smem);
    const int tid = threadIdx.x;
    const int wid = tid >> 5, lane = tid & 31;
    const int m0 = blockIdx.y * MT1;
    const int n0 = blockIdx.x * 128;
    const int wm = wid >> 1;            // 0..1 -> 64-row strip
    const int wn = wid & 1;             // 0..1 -> 64 cols
    const int g  = lane >> 2;
    const int q4 = lane & 3;

    float acc[4][8][4];
    #pragma unroll
    for (int i = 0; i < 4; i++)
        #pragma unroll
        for (int j = 0; j < 8; j++)
            #pragma unroll
            for (int r = 0; r < 4; r++) acc[i][j][r] = 0.f;

    const int nchunks = Kdim / 64;

    const int a_row = (lane & 7) + ((lane >> 3) & 1) * 8;
    const int a_g8  = lane >> 4;
    const int w_row = (lane & 7) + ((lane >> 4) & 1) * 8;
    const int w_g8  = (lane >> 3) & 1;

    auto prefetch = [&](int stage, int ch) {
        const int k0 = ch * 64;
        const uint32_t s0 = sb + (uint32_t)stage * STG1_EL * 2;
        const uint32_t sA = s0, sW = s0 + A1_EL*2;
        #pragma unroll
        for (int i = 0; i < 8; i++) {           // A: 1024 16B vecs / 128 thr
            int v = tid + i * 128;
            int row = v >> 3, q = v & 7;
            cpa16(sA + swz(row, q), A + (size_t)(m0 + row) * lda + k0 + q * 8);
        }
        #pragma unroll
        for (int i = 0; i < 8; i++) {           // W: 1024 vecs
            int v = tid + i * 128;
            int row = v >> 3, q = v & 7;
            cpa16(sW + swz(row, q), W + (size_t)(n0 + row) * Kdim + k0 + q * 8);
        }
        asm volatile("cp.async.commit_group;");
    };

    prefetch(0, 0);

    for (int ch = 0; ch < nchunks; ch++) {
        const int st = ch & 1;
        asm volatile("cp.async.wait_group 0;");
        __syncthreads();
        if (ch + 1 < nchunks) prefetch(st ^ 1, ch + 1);

        const uint32_t s0 = sb + (uint32_t)st * STG1_EL * 2;
        const uint32_t sA = s0, sW = s0 + A1_EL*2;

        #pragma unroll
        for (int ks = 0; ks < 4; ks++) {
            uint32_t ah[4][4];
            #pragma unroll
            for (int mf = 0; mf < 4; mf++) {
                int row = wm*64 + mf*16 + a_row;
                ldsm_x4(ah[mf], sA + swz(row, ks*2 + a_g8));
            }
            #pragma unroll
            for (int p = 0; p < 4; p++) {
                int nrow = wn*64 + p*16 + w_row;
                uint32_t bh[4];
                ldsm_x4(bh, sW + swz(nrow, ks*2 + w_g8));
                #pragma unroll
                for (int j = 0; j < 2; j++)
                    #pragma unroll
                    for (int mf = 0; mf < 4; mf++)
                        hmma(acc[mf][2*p+j], ah[mf], bh + 2*j);
            }
        }
    }

    #pragma unroll
    for (int mf = 0; mf < 4; mf++) {
        int row = m0 + wm*64 + mf*16 + g;
        #pragma unroll
        for (int nf = 0; nf < 8; nf++) {
            int col = n0 + wn*64 + nf*8 + q4*2;
            __half2 v0 = {__float2half_rn(acc[mf][nf][0]), __float2half_rn(acc[mf][nf][1])};
            __half2 v1 = {__float2half_rn(acc[mf][nf][2]), __float2half_rn(acc[mf][nf][3])};
            *(uint32_t*)&out[(size_t)row * ldc + col]       = *(uint32_t*)&v0;
            *(uint32_t*)&out[(size_t)(row + 8) * ldc + col] = *(uint32_t*)&v1;
        }
    }
}

// ---------------- GEMM variant B: 128x128 tile, 8 warps (32x64), 2 CTAs/SM, fp32 out ----------------
#define MT2 128
#define A2_EL (MT2*64)
#define W2_EL (128*64)
#define STG2_EL (A2_EL + W2_EL)
#define G2_SMEM (2*STG2_EL*2)        // 64 KB

__global__ __launch_bounds__(256, 2) void k_gemm2(
    const f16* __restrict__ A, int lda,
    const f16* __restrict__ W,
    float* __restrict__ out, int ldc, int Kdim)
{
    extern __shared__ f16 smem[];
    const uint32_t sb = smem_u32(smem);
    const int tid = threadIdx.x;
    const int wid = tid >> 5, lane = tid & 31;
    const int m0 = blockIdx.y * MT2;
    const int n0 = blockIdx.x * 128;
    const int wm = wid >> 1;            // 0..3 -> 32-row strip
    const int wn = wid & 1;             // 0..1 -> 64 cols
    const int g  = lane >> 2;
    const int q4 = lane & 3;

    float acc[2][8][4];
    #pragma unroll
    for (int i = 0; i < 2; i++)
        #pragma unroll
        for (int j = 0; j < 8; j++)
            #pragma unroll
            for (int r = 0; r < 4; r++) acc[i][j][r] = 0.f;

    const int nchunks = Kdim / 64;

    const int a_row = (lane & 7) + ((lane >> 3) & 1) * 8;
    const int a_g8  = lane >> 4;
    const int w_row = (lane & 7) + ((lane >> 4) & 1) * 8;
    const int w_g8  = (lane >> 3) & 1;

    auto prefetch = [&](int stage, int ch) {
        const int k0 = ch * 64;
        const uint32_t s0 = sb + (uint32_t)stage * STG2_EL * 2;
        const uint32_t sA = s0, sW = s0 + A2_EL*2;
        #pragma unroll
        for (int i = 0; i < 4; i++) {
            int v = tid + i * 256;
            int row = v >> 3, q = v & 7;
            cpa16(sA + swz(row, q), A + (size_t)(m0 + row) * lda + k0 + q * 8);
        }
        #pragma unroll
        for (int i = 0; i < 4; i++) {
            int v = tid + i * 256;
            int row = v >> 3, q = v & 7;
            cpa16(sW + swz(row, q), W + (size_t)(n0 + row) * Kdim + k0 + q * 8);
        }
        asm volatile("cp.async.commit_group;");
    };

    prefetch(0, 0);

    for (int ch = 0; ch < nchunks; ch++) {
        const int st = ch & 1;
        asm volatile("cp.async.wait_group 0;");
        __syncthreads();
        if (ch + 1 < nchunks) prefetch(st ^ 1, ch + 1);

        const uint32_t s0 = sb + (uint32_t)st * STG2_EL * 2;
        const uint32_t sA = s0, sW = s0 + A2_EL*2;

        #pragma unroll
        for (int ks = 0; ks < 4; ks++) {
            uint32_t ah[2][4];
            #pragma unroll
            for (int mf = 0; mf < 2; mf++) {
                int row = wm*32 + mf*16 + a_row;
                ldsm_x4(ah[mf], sA + swz(row, ks*2 + a_g8));
            }
            #pragma unroll
            for (int p = 0; p < 4; p++) {
                int nrow = wn*64 + p*16 + w_row;
                uint32_t bh[4];
                ldsm_x4(bh, sW + swz(nrow, ks*2 + w_g8));
                #pragma unroll
                for (int j = 0; j < 2; j++)
                    #pragma unroll
                    for (int mf = 0; mf < 2; mf++)
                        hmma(acc[mf][2*p+j], ah[mf], bh + 2*j);
            }
        }
    }

    #pragma unroll
    for (int mf = 0; mf < 2; mf++) {
        int row = m0 + wm*32 + mf*16 + g;
        #pragma unroll
        for (int nf = 0; nf < 8; nf++) {
            int col = n0 + wn*64 + nf*8 + q4*2;
            *(float2*)&out[(size_t)row * ldc + col]       = make_float2(acc[mf][nf][0], acc[mf][nf][1]);
            *(float2*)&out[(size_t)(row + 8) * ldc + col] = make_float2(acc[mf][nf][2], acc[mf][nf][3]);
        }
    }
}

// ---------------- scan pass 1: chunk end states (128 thr x 2 channels, half2) ----------------
__global__ __launch_bounds__(128) void k_scan1() {
    const int b = blockIdx.x / NCHUNK, c = blockIdx.x % NCHUNK;
    const int t = threadIdx.x;                  // owns n = 2t, 2t+1
    const float2 Ar = {g_Ar[2*t], g_Ar[2*t+1]};
    const float2 Ai = {g_Ai[2*t], g_Ai[2*t+1]};
    size_t base = ((size_t)b*SEQ + (size_t)c*CHUNK) * 512 + 2*t;
    float hr0 = 0.f, hi0 = 0.f, hr1 = 0.f, hi1 = 0.f;
    #pragma unroll 8
    for (int j = 0; j < CHUNK; j++) {
        __half2 ur2 = *(const __half2*)&g_u16[base];
        __half2 ui2 = *(const __half2*)&g_u16[base + 256];
        float2 ur = __half22float2(ur2), ui = __half22float2(ui2);
        float n0r = fmaf(Ar.x, hr0, fmaf(-Ai.x, hi0, ur.x));
        float n0i = fmaf(Ar.x, hi0, fmaf( Ai.x, hr0, ui.x));
        float n1r = fmaf(Ar.y, hr1, fmaf(-Ai.y, hi1, ur.y));
        float n1i = fmaf(Ar.y, hi1, fmaf( Ai.y, hr1, ui.y));
        hr0 = n0r; hi0 = n0i; hr1 = n1r; hi1 = n1i;
        base += 512;
    }
    int idx = (b*NCHUNK + c)*NST + 2*t;
    *(float2*)&g_cr[idx] = make_float2(hr0, hr1);
    *(float2*)&g_ci[idx] = make_float2(hi0, hi1);
}

// ---------------- scan pass 2: cross-chunk prefix ----------------
__global__ __launch_bounds__(256) void k_scan2() {
    const int b = blockIdx.x;
    const int n = threadIdx.x;
    const float Ar = g_ALr[n], Ai = g_ALi[n];
    float hr = 0.f, hi = 0.f;
    for (int cb = 0; cb < 4; cb++) {
        float cr[16], ci[16];
        #pragma unroll
        for (int i = 0; i < 16; i++) {
            int idx = (b*NCHUNK + cb*16 + i)*NST + n;
            cr[i] = g_cr[idx]; ci[i] = g_ci[idx];
        }
        #pragma unroll
        for (int i = 0; i < 16; i++) {
            int idx = (b*NCHUNK + cb*16 + i)*NST + n;
            g_pr[idx] = hr; g_pi[idx] = hi;
            float nhr = fmaf(Ar, hr, fmaf(-Ai, hi, cr[i]));
            float nhi = fmaf(Ar, hi, fmaf( Ai, hr, ci[i]));
            hr = nhr; hi = nhi;
        }
    }
}

// ---------------- scan pass 3: full scan with carry, emit h fp16 (128 thr x 2 ch) ----------------
__global__ __launch_bounds__(128) void k_scan3() {
    const int b = blockIdx.x / NCHUNK, c = blockIdx.x % NCHUNK;
    const int t = threadIdx.x;
    const float2 Ar = {g_Ar[2*t], g_Ar[2*t+1]};
    const float2 Ai = {g_Ai[2*t], g_Ai[2*t+1]};
    int pidx = (b*NCHUNK + c)*NST + 2*t;
    float2 pr = *(const float2*)&g_pr[pidx];
    float2 pi = *(const float2*)&g_pi[pidx];
    float hr0 = pr.x, hi0 = pi.x, hr1 = pr.y, hi1 = pi.y;
    size_t base = ((size_t)b*SEQ + (size_t)c*CHUNK) * 512 + 2*t;
    #pragma unroll 8
    for (int j = 0; j < CHUNK; j++) {
        __half2 ur2 = *(const __half2*)&g_u16[base];
        __half2 ui2 = *(const __half2*)&g_u16[base + 256];
        float2 ur = __half22float2(ur2), ui = __half22float2(ui2);
        float n0r = fmaf(Ar.x, hr0, fmaf(-Ai.x, hi0, ur.x));
        float n0i = fmaf(Ar.x, hi0, fmaf( Ai.x, hr0, ui.x));
        float n1r = fmaf(Ar.y, hr1, fmaf(-Ai.y, hi1, ur.y));
        float n1i = fmaf(Ar.y, hi1, fmaf( Ai.y, hr1, ui.y));
        hr0 = n0r; hi0 = n0i; hr1 = n1r; hi1 = n1i;
        __half2 hrv = {__float2half_rn(hr0), __float2half_rn(hr1)};
        __half2 hiv = {__float2half_rn(hi0), __float2half_rn(hi1)};
        *(uint32_t*)&g_h16[base]       = *(uint32_t*)&hrv;
        *(uint32_t*)&g_h16[base + 256] = *(uint32_t*)&hiv;
        base += 512;
    }
}

// ---------------- launch ----------------
extern "C" void kernel_launch(void* const* d_in, const int* in_sizes, int n_in,
                              void* d_out, int out_size) {
    const float* x   = (const float*)d_in[0];
    const float* llr = (const float*)d_in[1];
    const float* lim = (const float*)d_in[2];
    const float* ldt = (const float*)d_in[3];
    const float* Bm  = (const float*)d_in[4];
    const float* Cr  = (const float*)d_in[5];
    const float* Ci  = (const float*)d_in[6];
    float* out = (float*)d_out;

    cudaFuncSetAttribute(k_gemm1, cudaFuncAttributeMaxDynamicSharedMemorySize, G1_SMEM);
    cudaFuncSetAttribute(k_gemm2, cudaFuncAttributeMaxDynamicSharedMemorySize, G2_SMEM);

    f16 *x16, *w1, *w2, *h16, *u16;
    cudaGetSymbolAddress((void**)&x16, g_x16);
    cudaGetSymbolAddress((void**)&w1, g_W1);
    cudaGetSymbolAddress((void**)&w2, g_W2);
    cudaGetSymbolAddress((void**)&h16, g_h16);
    cudaGetSymbolAddress((void**)&u16, g_u16);

    k_setup<<<1, 256>>>(llr, lim, ldt);
    k_w1<<<(256*256)/256, 256>>>(Bm);
    k_w2<<<(256*512)/256, 256>>>(Cr, Ci);
    k_cvt<<<(M_TOT*DIN/4)/256, 256>>>(x);
    // GEMM1: u16[M,512] = x @ [Bbar_r;Bbar_i]^T   (fp16 output, 4-warp/3-CTA config)
    k_gemm1<<<dim3(512/128, M_TOT/MT1), 128, G1_SMEM>>>(x16, DIN, w1, u16, 512, DIN);
    k_scan1<<<BT*NCHUNK, 128>>>();
    k_scan2<<<BT, 256>>>();
    k_scan3<<<BT*NCHUNK, 128>>>();
    // GEMM2: out[M,256] = h @ [Cr|-Ci]^T   (fp32 output, 8-warp/2-CTA config)
    k_gemm2<<<dim3(DOUT/128, M_TOT/MT2), 256, G2_SMEM>>>(h16, 512, w2, out, DOUT, 512);
}

// round 17
// speedup vs baseline: 1.0512x; 1.0512x over previous
#include <cuda_runtime.h>
#include <cuda_fp16.h>
#include <cstdint>

#define BT 8
#define SEQ 4096
#define NST 256
#define DIN 256
#define DOUT 256
#define M_TOT (BT*SEQ)          // 32768
#define CHUNK 64
#define NCHUNK (SEQ/CHUNK)      // 64

typedef unsigned long long u64;
typedef __half f16;

// ---------------- device scratch ----------------
__device__ float g_Ar[NST], g_Ai[NST];
__device__ float g_ALr[NST], g_ALi[NST];
__device__ float g_wr[NST], g_wi[NST];
__device__ f16   g_x16[(size_t)M_TOT*DIN];
__device__ f16   g_W1[512*DIN];                 // [Bbar_r; Bbar_i] fp16
__device__ f16   g_W2[DOUT*512];                // [Cr | -Ci] fp16
__device__ f16   g_u16[(size_t)M_TOT*512];      // u fp16: [:,0:256]=real [:,256:512]=imag
__device__ f16   g_h16[(size_t)M_TOT*512];      // h fp16
__device__ float g_cr[BT*NCHUNK*NST], g_ci[BT*NCHUNK*NST];
__device__ float g_pr[BT*NCHUNK*NST], g_pi[BT*NCHUNK*NST];

// mma.sync m16n8k16 row.col fp16 -> f32 accumulate
__device__ __forceinline__ void hmma(float* d, const uint32_t* a, const uint32_t* b) {
    asm volatile(
        "mma.sync.aligned.m16n8k16.row.col.f32.f16.f16.f32 "
        "{%0,%1,%2,%3}, {%4,%5,%6,%7}, {%8,%9}, {%0,%1,%2,%3};"
        : "+f"(d[0]), "+f"(d[1]), "+f"(d[2]), "+f"(d[3])
        : "r"(a[0]), "r"(a[1]), "r"(a[2]), "r"(a[3]), "r"(b[0]), "r"(b[1]));
}
__device__ __forceinline__ void ldsm_x4(uint32_t* r, uint32_t addr) {
    asm volatile("ldmatrix.sync.aligned.m8n8.x4.shared.b16 {%0,%1,%2,%3}, [%4];"
        : "=r"(r[0]), "=r"(r[1]), "=r"(r[2]), "=r"(r[3]) : "r"(addr));
}
__device__ __forceinline__ void cpa16(uint32_t saddr, const void* g) {
    asm volatile("cp.async.cg.shared.global [%0], [%1], 16;" :: "r"(saddr), "l"(g));
}
__device__ __forceinline__ uint32_t smem_u32(const void* p) {
    uint32_t a;
    asm("{ .reg .u64 t; cvta.to.shared.u64 t, %1; cvt.u32.u64 %0, t; }" : "=r"(a) : "l"(p));
    return a;
}
// swizzled byte offset inside a R x 64 f16 tile
__device__ __forceinline__ uint32_t swz(int row, int g8) {
    return (uint32_t)(row * 64 + ((g8 ^ (row & 7)) * 8)) * 2;
}

// ---------------- setup: per-n scalars only ----------------
__global__ void k_setup(const float* __restrict__ llr, const float* __restrict__ lim,
                        const float* __restrict__ ldt) {
    int n = threadIdx.x;
    float lr = -expf(llr[n]);
    float li = lim[n];
    float dt = expf(ldt[n]);
    dt = fminf(fmaxf(dt, 0.005f), 0.1f);
    float dr = 1.f - 0.5f * dt * lr;
    float di = -0.5f * dt * li;
    float nr = 1.f + 0.5f * dt * lr;
    float ni = 0.5f * dt * li;
    float inv = 1.f / (dr*dr + di*di);
    float Ar = (nr*dr + ni*di) * inv;
    float Ai = (ni*dr - nr*di) * inv;
    g_Ar[n] = Ar; g_Ai[n] = Ai;
    g_wr[n] = dt * dr * inv;
    g_wi[n] = -dt * di * inv;
    float pr = 1.f, pi = 0.f;
    for (int j = 0; j < CHUNK; j++) {
        float t = pr*Ar - pi*Ai;
        pi = pr*Ai + pi*Ar;
        pr = t;
    }
    g_ALr[n] = pr; g_ALi[n] = pi;
}

// merged weight prep: blocks [0,256) -> W1 rows; blocks [256,768) -> W2
__global__ __launch_bounds__(256) void k_wb(const float* __restrict__ Bm,
                                            const float* __restrict__ Cr,
                                            const float* __restrict__ Ci) {
    int blk = blockIdx.x;
    int t = threadIdx.x;
    if (blk < 256) {
        int idx = blk * 256 + t;                // over 256*256
        int n = idx >> 8, k = idx & 255;
        float b = Bm[idx];
        g_W1[idx]             = __float2half_rn(g_wr[n] * b);
        g_W1[(256+n)*DIN + k] = __float2half_rn(g_wi[n] * b);
    } else {
        int idx = (blk - 256) * 256 + t;        // over 256*512
        int d = idx >> 9, k = idx & 511;
        float v = (k < 256) ? Cr[d*256 + k] : -Ci[d*256 + (k - 256)];
        g_W2[idx] = __float2half_rn(v);
    }
}

// x -> fp16, 8 elements/thread
__global__ __launch_bounds__(256) void k_cvt(const float* __restrict__ x) {
    size_t i = (size_t)(blockIdx.x * blockDim.x + threadIdx.x) * 8;
    float4 v0 = *(const float4*)&x[i];
    float4 v1 = *(const float4*)&x[i + 4];
    __half2 a0 = {__float2half_rn(v0.x), __float2half_rn(v0.y)};
    __half2 b0 = {__float2half_rn(v0.z), __float2half_rn(v0.w)};
    __half2 a1 = {__float2half_rn(v1.x), __float2half_rn(v1.y)};
    __half2 b1 = {__float2half_rn(v1.z), __float2half_rn(v1.w)};
    *(uint4*)&g_x16[i] = make_uint4(*(uint32_t*)&a0, *(uint32_t*)&b0,
                                    *(uint32_t*)&a1, *(uint32_t*)&b1);
}

// ---------------- HMMA GEMM: 128x128 tile, 8 warps (32x64), 2 CTAs/SM ----------------
// OUT16: write fp16 (half2), else fp32.
#define MT 128
#define A_EL (MT*64)
#define W_EL (128*64)
#define STAGE_EL (A_EL + W_EL)
#define GEMM_SMEM (2*STAGE_EL*2)     // 64 KB

template<bool OUT16>
__global__ __launch_bounds__(256, 2) void k_gemm(
    const f16* __restrict__ A, int lda,
    const f16* __restrict__ W,
    void* __restrict__ outv, int ldc, int Kdim)
{
    extern __shared__ f16 smem[];
    const uint32_t sb = smem_u32(smem);
    const int tid = threadIdx.x;
    const int wid = tid >> 5, lane = tid & 31;
    const int m0 = blockIdx.y * MT;
    const int n0 = blockIdx.x * 128;
    const int wm = wid >> 1;            // 0..3 -> 32-row strip
    const int wn = wid & 1;             // 0..1 -> 64 cols
    const int g  = lane >> 2;
    const int q4 = lane & 3;

    float acc[2][8][4];
    #pragma unroll
    for (int i = 0; i < 2; i++)
        #pragma unroll
        for (int j = 0; j < 8; j++)
            #pragma unroll
            for (int r = 0; r < 4; r++) acc[i][j][r] = 0.f;

    const int nchunks = Kdim / 64;

    const int a_row = (lane & 7) + ((lane >> 3) & 1) * 8;
    const int a_g8  = lane >> 4;
    const int w_row = (lane & 7) + ((lane >> 4) & 1) * 8;
    const int w_g8  = (lane >> 3) & 1;

    auto prefetch = [&](int stage, int ch) {
        const int k0 = ch * 64;
        const uint32_t s0 = sb + (uint32_t)stage * STAGE_EL * 2;
        const uint32_t sA = s0, sW = s0 + A_EL*2;
        #pragma unroll
        for (int i = 0; i < 4; i++) {           // A: 1024 16B vecs
            int v = tid + i * 256;
            int row = v >> 3, q = v & 7;
            cpa16(sA + swz(row, q), A + (size_t)(m0 + row) * lda + k0 + q * 8);
        }
        #pragma unroll
        for (int i = 0; i < 4; i++) {           // W: 1024 vecs
            int v = tid + i * 256;
            int row = v >> 3, q = v & 7;
            cpa16(sW + swz(row, q), W + (size_t)(n0 + row) * Kdim + k0 + q * 8);
        }
        asm volatile("cp.async.commit_group;");
    };

    prefetch(0, 0);

    for (int ch = 0; ch < nchunks; ch++) {
        const int st = ch & 1;
        asm volatile("cp.async.wait_group 0;");
        __syncthreads();
        if (ch + 1 < nchunks) prefetch(st ^ 1, ch + 1);

        const uint32_t s0 = sb + (uint32_t)st * STAGE_EL * 2;
        const uint32_t sA = s0, sW = s0 + A_EL*2;

        #pragma unroll
        for (int ks = 0; ks < 4; ks++) {
            uint32_t ah[2][4];
            #pragma unroll
            for (int mf = 0; mf < 2; mf++) {
                int row = wm*32 + mf*16 + a_row;
                ldsm_x4(ah[mf], sA + swz(row, ks*2 + a_g8));
            }
            #pragma unroll
            for (int p = 0; p < 4; p++) {
                int nrow = wn*64 + p*16 + w_row;
                uint32_t bh[4];
                ldsm_x4(bh, sW + swz(nrow, ks*2 + w_g8));
                #pragma unroll
                for (int j = 0; j < 2; j++)
                    #pragma unroll
                    for (int mf = 0; mf < 2; mf++)
                        hmma(acc[mf][2*p+j], ah[mf], bh + 2*j);
            }
        }
    }

    #pragma unroll
    for (int mf = 0; mf < 2; mf++) {
        int row = m0 + wm*32 + mf*16 + g;
        #pragma unroll
        for (int nf = 0; nf < 8; nf++) {
            int col = n0 + wn*64 + nf*8 + q4*2;
            if (OUT16) {
                f16* out = (f16*)outv;
                __half2 v0 = {__float2half_rn(acc[mf][nf][0]), __float2half_rn(acc[mf][nf][1])};
                __half2 v1 = {__float2half_rn(acc[mf][nf][2]), __float2half_rn(acc[mf][nf][3])};
                *(uint32_t*)&out[(size_t)row * ldc + col]       = *(uint32_t*)&v0;
                *(uint32_t*)&out[(size_t)(row + 8) * ldc + col] = *(uint32_t*)&v1;
            } else {
                float* out = (float*)outv;
                *(float2*)&out[(size_t)row * ldc + col]       = make_float2(acc[mf][nf][0], acc[mf][nf][1]);
                *(float2*)&out[(size_t)(row + 8) * ldc + col] = make_float2(acc[mf][nf][2], acc[mf][nf][3]);
            }
        }
    }
}

// ---------------- scan pass 1: chunk end states (128 thr x 2 channels, half2) ----------------
__global__ __launch_bounds__(128) void k_scan1() {
    const int b = blockIdx.x / NCHUNK, c = blockIdx.x % NCHUNK;
    const int t = threadIdx.x;                  // owns n = 2t, 2t+1
    const float2 Ar = {g_Ar[2*t], g_Ar[2*t+1]};
    const float2 Ai = {g_Ai[2*t], g_Ai[2*t+1]};
    size_t base = ((size_t)b*SEQ + (size_t)c*CHUNK) * 512 + 2*t;
    float hr0 = 0.f, hi0 = 0.f, hr1 = 0.f, hi1 = 0.f;
    #pragma unroll 8
    for (int j = 0; j < CHUNK; j++) {
        __half2 ur2 = *(const __half2*)&g_u16[base];
        __half2 ui2 = *(const __half2*)&g_u16[base + 256];
        float2 ur = __half22float2(ur2), ui = __half22float2(ui2);
        float n0r = fmaf(Ar.x, hr0, fmaf(-Ai.x, hi0, ur.x));
        float n0i = fmaf(Ar.x, hi0, fmaf( Ai.x, hr0, ui.x));
        float n1r = fmaf(Ar.y, hr1, fmaf(-Ai.y, hi1, ur.y));
        float n1i = fmaf(Ar.y, hi1, fmaf( Ai.y, hr1, ui.y));
        hr0 = n0r; hi0 = n0i; hr1 = n1r; hi1 = n1i;
        base += 512;
    }
    int idx = (b*NCHUNK + c)*NST + 2*t;
    *(float2*)&g_cr[idx] = make_float2(hr0, hr1);
    *(float2*)&g_ci[idx] = make_float2(hi0, hi1);
}

// ---------------- scan pass 2: cross-chunk prefix ----------------
__global__ __launch_bounds__(256) void k_scan2() {
    const int b = blockIdx.x;
    const int n = threadIdx.x;
    const float Ar = g_ALr[n], Ai = g_ALi[n];
    float hr = 0.f, hi = 0.f;
    for (int cb = 0; cb < 4; cb++) {
        float cr[16], ci[16];
        #pragma unroll
        for (int i = 0; i < 16; i++) {
            int idx = (b*NCHUNK + cb*16 + i)*NST + n;
            cr[i] = g_cr[idx]; ci[i] = g_ci[idx];
        }
        #pragma unroll
        for (int i = 0; i < 16; i++) {
            int idx = (b*NCHUNK + cb*16 + i)*NST + n;
            g_pr[idx] = hr; g_pi[idx] = hi;
            float nhr = fmaf(Ar, hr, fmaf(-Ai, hi, cr[i]));
            float nhi = fmaf(Ar, hi, fmaf( Ai, hr, ci[i]));
            hr = nhr; hi = nhi;
        }
    }
}

// ---------------- scan pass 3: full scan with carry, emit h fp16 (128 thr x 2 ch) ----------------
__global__ __launch_bounds__(128) void k_scan3() {
    const int b = blockIdx.x / NCHUNK, c = blockIdx.x % NCHUNK;
    const int t = threadIdx.x;
    const float2 Ar = {g_Ar[2*t], g_Ar[2*t+1]};
    const float2 Ai = {g_Ai[2*t], g_Ai[2*t+1]};
    int pidx = (b*NCHUNK + c)*NST + 2*t;
    float2 pr = *(const float2*)&g_pr[pidx];
    float2 pi = *(const float2*)&g_pi[pidx];
    float hr0 = pr.x, hi0 = pi.x, hr1 = pr.y, hi1 = pi.y;
    size_t base = ((size_t)b*SEQ + (size_t)c*CHUNK) * 512 + 2*t;
    #pragma unroll 8
    for (int j = 0; j < CHUNK; j++) {
        __half2 ur2 = *(const __half2*)&g_u16[base];
        __half2 ui2 = *(const __half2*)&g_u16[base + 256];
        float2 ur = __half22float2(ur2), ui = __half22float2(ui2);
        float n0r = fmaf(Ar.x, hr0, fmaf(-Ai.x, hi0, ur.x));
        float n0i = fmaf(Ar.x, hi0, fmaf( Ai.x, hr0, ui.x));
        float n1r = fmaf(Ar.y, hr1, fmaf(-Ai.y, hi1, ur.y));
        float n1i = fmaf(Ar.y, hi1, fmaf( Ai.y, hr1, ui.y));
        hr0 = n0r; hi0 = n0i; hr1 = n1r; hi1 = n1i;
        __half2 hrv = {__float2half_rn(hr0), __float2half_rn(hr1)};
        __half2 hiv = {__float2half_rn(hi0), __float2half_rn(hi1)};
        *(uint32_t*)&g_h16[base]       = *(uint32_t*)&hrv;
        *(uint32_t*)&g_h16[base + 256] = *(uint32_t*)&hiv;
        base += 512;
    }
}

// ---------------- launch ----------------
extern "C" void kernel_launch(void* const* d_in, const int* in_sizes, int n_in,
                              void* d_out, int out_size) {
    const float* x   = (const float*)d_in[0];
    const float* llr = (const float*)d_in[1];
    const float* lim = (const float*)d_in[2];
    const float* ldt = (const float*)d_in[3];
    const float* Bm  = (const float*)d_in[4];
    const float* Cr  = (const float*)d_in[5];
    const float* Ci  = (const float*)d_in[6];
    float* out = (float*)d_out;

    cudaFuncSetAttribute(k_gemm<true>,  cudaFuncAttributeMaxDynamicSharedMemorySize, GEMM_SMEM);
    cudaFuncSetAttribute(k_gemm<false>, cudaFuncAttributeMaxDynamicSharedMemorySize, GEMM_SMEM);

    f16 *x16, *w1, *w2, *h16, *u16;
    cudaGetSymbolAddress((void**)&x16, g_x16);
    cudaGetSymbolAddress((void**)&w1, g_W1);
    cudaGetSymbolAddress((void**)&w2, g_W2);
    cudaGetSymbolAddress((void**)&h16, g_h16);
    cudaGetSymbolAddress((void**)&u16, g_u16);

    k_setup<<<1, 256>>>(llr, lim, ldt);
    k_wb<<<768, 256>>>(Bm, Cr, Ci);
    k_cvt<<<(M_TOT*DIN/8)/256, 256>>>(x);
    // GEMM1: u16[M,512] = x @ [Bbar_r;Bbar_i]^T   (fp16 output)
    k_gemm<true><<<dim3(512/128, M_TOT/MT), 256, GEMM_SMEM>>>(x16, DIN, w1, u16, 512, DIN);
    k_scan1<<<BT*NCHUNK, 128>>>();
    k_scan2<<<BT, 256>>>();
    k_scan3<<<BT*NCHUNK, 128>>>();
    // GEMM2: out[M,256] = h @ [Cr|-Ci]^T   (fp32 output)
    k_gemm<false><<<dim3(DOUT/128, M_TOT/MT), 256, GEMM_SMEM>>>(h16, 512, w2, out, DOUT, 512);
}